// round 1
// baseline (speedup 1.0000x reference)
#include <cuda_runtime.h>
#include <cstdint>

#define FFT_N 512
#define NBIN (FFT_N * FFT_N)
#define N_C 3
#define N_K 8
#define N_V 9
#define NIMG_X (N_C * N_K)   // 24
#define NIMG_Y (N_C * N_V)   // 27
#define PI_F 3.14159265358979323846f

// ---------------- scratch (static device globals; no cudaMalloc allowed) ----
__device__ float2 d_Xs[(size_t)NIMG_X * NBIN];   // X spectrum, reused as FDL spectrum
__device__ float2 d_Ys[(size_t)NIMG_Y * NBIN];   // Y spectrum
__device__ float2 d_tw[FFT_N / 2];               // forward twiddles W_512^j
__device__ float4 d_etab[FFT_N];                 // per-freq (exp(i*delta*w), exp(-i*d0*w))

// ---------------- complex helpers -------------------------------------------
__device__ __forceinline__ float2 cmulf2(float2 a, float2 b) {
    return make_float2(fmaf(a.x, b.x, -a.y * b.y), fmaf(a.x, b.y, a.y * b.x));
}
__device__ __forceinline__ float2 caddf2(float2 a, float2 b) { return make_float2(a.x + b.x, a.y + b.y); }
__device__ __forceinline__ float2 csubf2(float2 a, float2 b) { return make_float2(a.x - b.x, a.y - b.y); }
__device__ __forceinline__ float2 cconjf2(float2 a) { return make_float2(a.x, -a.y); }

// z^s for s in {-1, 0, 1} (uniform across warp: s is per-view constant)
__device__ __forceinline__ float2 cpowi(float2 z, float s) {
    if (s > 0.5f) return z;
    if (s < -0.5f) return cconjf2(z);
    return make_float2(1.f, 0.f);
}

// ---------------- table fill -------------------------------------------------
__global__ void fill_tables(const float* __restrict__ dp) {
    int j = threadIdx.x;
    if (j < FFT_N / 2) {
        float ang = -2.f * PI_F * (float)j / (float)FFT_N;
        float s, c;
        sincosf(ang, &s, &c);
        d_tw[j] = make_float2(c, s);
    }
    if (j < FFT_N) {
        float cf = (j < FFT_N / 2) ? (float)j : (float)(j - FFT_N);  // centered freq index
        float w = cf * (2.f * PI_F / (float)FFT_N);
        float delta = dp[1] - dp[0];
        float d0 = dp[0];
        float s1, c1, s2, c2;
        sincosf(delta * w, &s1, &c1);   // exp(+i*delta*w)
        sincosf(-d0 * w, &s2, &c2);     // exp(-i*d0*w)
        d_etab[j] = make_float4(c1, s1, c2, s2);
    }
}

// ---------------- 512-pt Stockham radix-2 FFT in shared memory ---------------
// 128 threads per transform (t in [0,128)), 2 butterflies/thread/stage.
// 9 stages (odd) -> result lands in the buffer passed as `b`.
template <int INV>
__device__ __forceinline__ void fft512(float2* a, float2* b, int t) {
#pragma unroll
    for (int s = 0; s < 9; s++) {
        const int m = 1 << s;
#pragma unroll
        for (int h = 0; h < 2; h++) {
            int i = t + (h << 7);          // i = j*m + k, i in [0,256)
            int jm = i & ~(m - 1);         // j*m  (twiddle index, < 256)
            float2 u0 = a[i];
            float2 u1 = a[i + 256];
            float2 tw = d_tw[jm];
            if (INV) tw.y = -tw.y;
            float2 sm = caddf2(u0, u1);
            float2 df = csubf2(u0, u1);
            b[jm + i] = sm;                 // 2*j*m + k
            b[jm + i + m] = cmulf2(tw, df); // (2*j+1)*m + k
        }
        __syncthreads();
        float2* tmp = a; a = b; b = tmp;
    }
}

// ---------------- row FFT: real input -> complex spectrum (along W) ----------
template <int WHICH>  // 0 -> d_Xs, 1 -> d_Ys
__global__ void fwd_rows_r2c(const float* __restrict__ in) {
    __shared__ float2 s0[2][FFT_N];
    __shared__ float2 s1[2][FFT_N];
    int sub = threadIdx.x >> 7;
    int t = threadIdx.x & 127;
    size_t line = (size_t)blockIdx.x * 2 + sub;
    const float* src = in + line * FFT_N;
    float2* dst = (WHICH ? d_Ys : d_Xs) + line * FFT_N;
#pragma unroll
    for (int i = t; i < FFT_N; i += 128) s0[sub][i] = make_float2(src[i], 0.f);
    __syncthreads();
    fft512<0>(s0[sub], s1[sub], t);
#pragma unroll
    for (int i = t; i < FFT_N; i += 128) dst[i] = s1[sub][i];
}

// ---------------- column FFT (along H), in-place, 4 columns per block --------
template <int WHICH, int INV>
__global__ void fft_cols() {
    __shared__ float2 s0[4][FFT_N];
    __shared__ float2 s1[4][FFT_N];
    float2* data = (WHICH ? d_Ys : d_Xs);
    float2* base = data + (size_t)blockIdx.y * NBIN + (size_t)blockIdx.x * 4;
    int t = threadIdx.x;          // 512 threads
    int c = t & 3, r0 = t >> 2;   // load mapping: 32B sectors fully used
#pragma unroll
    for (int i = 0; i < 4; i++) {
        int r = r0 + i * 128;
        s0[c][r] = base[(size_t)r * FFT_N + c];
    }
    __syncthreads();
    int col = t >> 7, lane = t & 127;
    fft512<INV>(s0[col], s1[col], lane);
#pragma unroll
    for (int i = 0; i < 4; i++) {
        int r = r0 + i * 128;
        base[(size_t)r * FFT_N + c] = s1[c][r];
    }
}

// ---------------- inverse row FFT: complex -> real output, scaled ------------
__global__ void inv_rows_c2r(float* __restrict__ out) {
    __shared__ float2 s0[2][FFT_N];
    __shared__ float2 s1[2][FFT_N];
    int sub = threadIdx.x >> 7;
    int t = threadIdx.x & 127;
    size_t line = (size_t)blockIdx.x * 2 + sub;
    const float2* src = d_Xs + line * FFT_N;
    float* dst = out + line * FFT_N;
#pragma unroll
    for (int i = t; i < FFT_N; i += 128) s0[sub][i] = src[i];
    __syncthreads();
    fft512<1>(s0[sub], s1[sub], t);
    const float sc = 1.f / (float)NBIN;
#pragma unroll
    for (int i = t; i < FFT_N; i += 128) dst[i] = s1[sub][i].x * sc;
}

// ---------------- per-bin FDL solve ------------------------------------------
// For each bin: M = ATA + rho*I (8x8 Hermitian Toeplitz, HPD), rhs_c = A^H Y_c + rho*X_c.
// Cholesky once, forward/back solve per channel. Writes FDL spectrum in-place into d_Xs.
// Bins (ky==256, 1<=kx<=255) are zeroed to match the reference's unfilled padding row.
__global__ void __launch_bounds__(128) solve_kernel(const float* __restrict__ up,
                                                    const float* __restrict__ vp,
                                                    const float* __restrict__ rhop) {
    int bin = blockIdx.x * blockDim.x + threadIdx.x;
    int kx = bin & (FFT_N - 1);
    int ky = bin >> 9;
    float rho = rhop[0];

    if (ky == 256 && kx >= 1 && kx <= 255) {
        float2 z0 = make_float2(0.f, 0.f);
#pragma unroll
        for (int i = 0; i < NIMG_X; i++) d_Xs[(size_t)i * NBIN + bin] = z0;
        return;
    }

    float4 ex = d_etab[kx];
    float4 ey = d_etab[ky];
    float2 Edx = make_float2(ex.x, ex.y), E0x = make_float2(ex.z, ex.w);
    float2 Edy = make_float2(ey.x, ey.y), E0y = make_float2(ey.z, ey.w);

    float2 t[8];
#pragma unroll
    for (int m = 1; m < 8; m++) t[m] = make_float2(0.f, 0.f);

    float2 rhs[N_C][N_K];
#pragma unroll
    for (int c = 0; c < N_C; c++)
#pragma unroll
        for (int k = 0; k < N_K; k++) {
            float2 xv = d_Xs[((size_t)(c * N_K + k)) * NBIN + bin];
            rhs[c][k] = make_float2(rho * xv.x, rho * xv.y);
        }

#pragma unroll
    for (int vi = 0; vi < N_V; vi++) {
        float uu = up[vi], vv = vp[vi];
        float2 e  = cmulf2(cpowi(Edx, uu), cpowi(Edy, vv));   // exp(+i*delta*s_v)
        float2 e0 = cmulf2(cpowi(E0x, uu), cpowi(E0y, vv));   // exp(-i*d0*s_v)

        // Toeplitz generators t[m] = sum_v exp(i*m*delta*s_v)
        float2 p = e;
#pragma unroll
        for (int m = 1; m < 8; m++) { t[m] = caddf2(t[m], p); p = cmulf2(p, e); }

        float2 yv[N_C];
#pragma unroll
        for (int c = 0; c < N_C; c++) yv[c] = d_Ys[((size_t)(c * N_V + vi)) * NBIN + bin];

        // conj(A[v,k]) = e0 * conj(e)^k  ;  rhs[c][k] += conj(A[v,k]) * Y[c][v]
        float2 ak = e0;
        float2 ec = cconjf2(e);
#pragma unroll
        for (int k = 0; k < N_K; k++) {
#pragma unroll
            for (int c = 0; c < N_C; c++) {
                rhs[c][k].x = fmaf(ak.x, yv[c].x, fmaf(-ak.y, yv[c].y, rhs[c][k].x));
                rhs[c][k].y = fmaf(ak.x, yv[c].y, fmaf(ak.y, yv[c].x, rhs[c][k].y));
            }
            ak = cmulf2(ak, ec);
        }
    }

    // Cholesky: M[k][l] = conj(t[k-l]) for k>l ; M[l][l] = V + rho (real)
    float2 L[8][8];
    float di[8];
#pragma unroll
    for (int l = 0; l < 8; l++) {
        float ds = (float)N_V + rho;
#pragma unroll
        for (int j = 0; j < l; j++)
            ds -= L[l][j].x * L[l][j].x + L[l][j].y * L[l][j].y;
        float dl = sqrtf(ds);
        float inv = 1.f / dl;
        di[l] = inv;
#pragma unroll
        for (int k = l + 1; k < 8; k++) {
            float2 s = cconjf2(t[k - l]);
#pragma unroll
            for (int j = 0; j < l; j++)
                s = csubf2(s, cmulf2(L[k][j], cconjf2(L[l][j])));
            L[k][l] = make_float2(s.x * inv, s.y * inv);
        }
    }

    // Per-channel forward/back substitution
#pragma unroll
    for (int c = 0; c < N_C; c++) {
        float2 w[8];
#pragma unroll
        for (int l = 0; l < 8; l++) {
            float2 s = rhs[c][l];
#pragma unroll
            for (int j = 0; j < l; j++) s = csubf2(s, cmulf2(L[l][j], w[j]));
            w[l] = make_float2(s.x * di[l], s.y * di[l]);
        }
        float2 z[8];
#pragma unroll
        for (int k = 7; k >= 0; k--) {
            float2 s = w[k];
#pragma unroll
            for (int j = k + 1; j < 8; j++) s = csubf2(s, cmulf2(cconjf2(L[j][k]), z[j]));
            z[k] = make_float2(s.x * di[k], s.y * di[k]);
        }
#pragma unroll
        for (int k = 0; k < N_K; k++)
            d_Xs[((size_t)(c * N_K + k)) * NBIN + bin] = z[k];
    }
}

// ---------------- launch ------------------------------------------------------
extern "C" void kernel_launch(void* const* d_in, const int* in_sizes, int n_in,
                              void* d_out, int out_size) {
    const float* x   = (const float*)d_in[0];  // [1,3,8,512,512]
    const float* y   = (const float*)d_in[1];  // [1,3,9,512,512]
    const float* u   = (const float*)d_in[2];  // [9]
    const float* v   = (const float*)d_in[3];  // [9]
    const float* dd  = (const float*)d_in[4];  // [8]
    const float* rho = (const float*)d_in[5];  // [1]
    float* out = (float*)d_out;                // [1,3,8,512,512] float32

    fill_tables<<<1, 512>>>(dd);

    // forward FFT2 (rows along W, then columns along H)
    fwd_rows_r2c<0><<<NIMG_X * (FFT_N / 2), 256>>>(x);
    fwd_rows_r2c<1><<<NIMG_Y * (FFT_N / 2), 256>>>(y);
    fft_cols<0, 0><<<dim3(FFT_N / 4, NIMG_X), 512>>>();
    fft_cols<1, 0><<<dim3(FFT_N / 4, NIMG_Y), 512>>>();

    // per-frequency regularized least-squares solve (in-place into d_Xs)
    solve_kernel<<<NBIN / 128, 128>>>(u, v, rho);

    // inverse FFT2, write real part scaled by 1/(H*W)
    fft_cols<0, 1><<<dim3(FFT_N / 4, NIMG_X), 512>>>();
    inv_rows_c2r<<<NIMG_X * (FFT_N / 2), 256>>>(out);
}

// round 4
// speedup vs baseline: 1.7651x; 1.7651x over previous
#include <cuda_runtime.h>
#include <cstdint>

#define FFT_N 512
#define NBIN (FFT_N * FFT_N)
#define N_C 3
#define N_K 8
#define N_V 9
#define NIMG_X (N_C * N_K)   // 24
#define NIMG_Y (N_C * N_V)   // 27
#define PI_F 3.14159265358979323846f

// ---------------- scratch (static device globals; no cudaMalloc allowed) ----
__device__ float2 d_Xs[(size_t)NIMG_X * NBIN];   // X spectrum, reused as FDL spectrum
__device__ float2 d_Ys[(size_t)NIMG_Y * NBIN];   // Y spectrum
__device__ float2 d_tw[256];                     // W_512^j, j in [0,256)
__device__ float4 d_etab[FFT_N];                 // per-freq (exp(i*delta*w), exp(-i*d0*w))

// ---------------- complex helpers -------------------------------------------
__device__ __forceinline__ float2 cmulf2(float2 a, float2 b) {
    return make_float2(fmaf(a.x, b.x, -a.y * b.y), fmaf(a.x, b.y, a.y * b.x));
}
__device__ __forceinline__ float2 caddf2(float2 a, float2 b) { return make_float2(a.x + b.x, a.y + b.y); }
__device__ __forceinline__ float2 csubf2(float2 a, float2 b) { return make_float2(a.x - b.x, a.y - b.y); }
__device__ __forceinline__ float2 cconjf2(float2 a) { return make_float2(a.x, -a.y); }

__device__ __forceinline__ float2 cpowi(float2 z, float s) {
    if (s > 0.5f) return z;
    if (s < -0.5f) return cconjf2(z);
    return make_float2(1.f, 0.f);
}

// ---------------- table fill -------------------------------------------------
__global__ void fill_tables(const float* __restrict__ dp) {
    int j = threadIdx.x;
    if (j < 256) {
        float ang = -2.f * PI_F * (float)j / (float)FFT_N;
        float s, c;
        sincosf(ang, &s, &c);
        d_tw[j] = make_float2(c, s);
    }
    if (j < FFT_N) {
        float cf = (j < FFT_N / 2) ? (float)j : (float)(j - FFT_N);  // centered freq index
        float w = cf * (2.f * PI_F / (float)FFT_N);
        float delta = dp[1] - dp[0];
        float d0 = dp[0];
        float s1, c1, s2, c2;
        sincosf(delta * w, &s1, &c1);   // exp(+i*delta*w)
        sincosf(-d0 * w, &s2, &c2);     // exp(-i*d0*w)
        d_etab[j] = make_float4(c1, s1, c2, s2);
    }
}

// ---------------- register radix-8 butterflies --------------------------------
template <int INV>
__device__ __forceinline__ void fft4x(float2 v[4]) {
    float2 e0 = caddf2(v[0], v[2]), e1 = caddf2(v[1], v[3]);
    float2 o0 = csubf2(v[0], v[2]), o1 = csubf2(v[1], v[3]);
    o1 = INV ? make_float2(-o1.y, o1.x) : make_float2(o1.y, -o1.x);  // *(+-i)
    v[0] = caddf2(e0, e1); v[2] = csubf2(e0, e1);
    v[1] = caddf2(o0, o1); v[3] = csubf2(o0, o1);
}

template <int INV>
__device__ __forceinline__ void fft8(float2 a[8]) {
    const float C = 0.70710678118654752440f;
    float2 s[4], d[4];
#pragma unroll
    for (int k = 0; k < 4; k++) { s[k] = caddf2(a[k], a[k + 4]); d[k] = csubf2(a[k], a[k + 4]); }
    if (INV) {
        d[1] = cmulf2(d[1], make_float2(C, C));
        d[2] = make_float2(-d[2].y, d[2].x);
        d[3] = cmulf2(d[3], make_float2(-C, C));
    } else {
        d[1] = cmulf2(d[1], make_float2(C, -C));
        d[2] = make_float2(d[2].y, -d[2].x);
        d[3] = cmulf2(d[3], make_float2(-C, -C));
    }
    fft4x<INV>(s);
    fft4x<INV>(d);
    a[0] = s[0]; a[2] = s[1]; a[4] = s[2]; a[6] = s[3];
    a[1] = d[0]; a[3] = d[1]; a[5] = d[2]; a[7] = d[3];
}

// ---------------- 512-pt FFT: 64 threads, 8 regs, 2 shared exchanges ----------
// In:  a[j]  = x[t + 64*j],  t in [0,64)
// Out: a[m1] = X[t + 64*m1]
// sA layout:  [k0*72 + t]            (576 floats per component)
// sB layout:  [9*k0 + 72*m0 + r]     (576 floats per component)
template <int INV>
__device__ __forceinline__ void fft512r8(float2 a[8], int t,
                                         float* sAre, float* sAim,
                                         float* sBre, float* sBim) {
    fft8<INV>(a);
    {   // a[k0] *= W512^{t*k0}
        float2 w = d_tw[t]; if (INV) w.y = -w.y;
        float2 p = w;
#pragma unroll
        for (int k = 1; k < 8; k++) { a[k] = cmulf2(a[k], p); p = cmulf2(p, w); }
    }
#pragma unroll
    for (int k = 0; k < 8; k++) { sAre[k * 72 + t] = a[k].x; sAim[k * 72 + t] = a[k].y; }
    __syncthreads();
    int hi = t >> 3, lo = t & 7;
#pragma unroll
    for (int j = 0; j < 8; j++) {
        int idx = hi * 72 + 8 * j + lo;
        a[j] = make_float2(sAre[idx], sAim[idx]);
    }
    fft8<INV>(a);
    {   // a[m0] *= W64^{lo*m0} = W512^{8*lo*m0}
        float2 w = d_tw[8 * lo]; if (INV) w.y = -w.y;
        float2 p = w;
#pragma unroll
        for (int m = 1; m < 8; m++) { a[m] = cmulf2(a[m], p); p = cmulf2(p, w); }
    }
#pragma unroll
    for (int m = 0; m < 8; m++) {
        int idx = 9 * hi + 72 * m + lo;
        sBre[idx] = a[m].x; sBim[idx] = a[m].y;
    }
    __syncthreads();
#pragma unroll
    for (int r = 0; r < 8; r++) {
        int idx = 9 * lo + 72 * hi + r;
        a[r] = make_float2(sBre[idx], sBim[idx]);
    }
    fft8<INV>(a);
}

// ---------------- row FFT: real input -> full spectrum (along W) --------------
template <int WHICH>  // 0 -> d_Xs, 1 -> d_Ys
__global__ void fwd_rows(const float* __restrict__ in) {
    __shared__ float sA[4][2][576];
    __shared__ float sB[4][2][576];
    int sub = threadIdx.x >> 6;       // 4 rows per 256-thread block
    int t = threadIdx.x & 63;
    size_t line = (size_t)blockIdx.x * 4 + sub;
    const float* src = in + line * FFT_N;
    float2* dst = (WHICH ? d_Ys : d_Xs) + line * FFT_N;
    float2 a[8];
#pragma unroll
    for (int j = 0; j < 8; j++) a[j] = make_float2(src[t + 64 * j], 0.f);
    fft512r8<0>(a, t, sA[sub][0], sA[sub][1], sB[sub][0], sB[sub][1]);
#pragma unroll
    for (int m = 0; m < 8; m++) dst[t + 64 * m] = a[m];
}

// ---------------- column FFT (along H), in-place, 4 columns per block ---------
// slice stride 1160 floats (== 8 mod 32: conflict-free for the c = tid&3
// interleave in all four exchange phases).
template <int WHICH, int INV>
__global__ void fft_cols(void) {
    __shared__ float sA[4 * 1160];
    __shared__ float sB[4 * 1160];
    float2* data = (WHICH ? d_Ys : d_Xs) + (size_t)blockIdx.y * NBIN;
    int c = threadIdx.x & 3;
    int t = threadIdx.x >> 2;         // [0,64)
    int kx = blockIdx.x * 4 + c;
    float2* col = data + kx;
    float2 a[8];
#pragma unroll
    for (int j = 0; j < 8; j++)
        a[j] = col[(size_t)(t + 64 * j) * FFT_N];
    float* base = sA + c * 1160;
    float* baseB = sB + c * 1160;
    fft512r8<INV>(a, t, base, base + 576, baseB, baseB + 576);
#pragma unroll
    for (int m = 0; m < 8; m++)
        col[(size_t)(t + 64 * m) * FFT_N] = a[m];
}

// ---------------- inverse row FFT: full spectrum -> real output ---------------
__global__ void inv_rows(float* __restrict__ out) {
    __shared__ float sA[4][2][576];
    __shared__ float sB[4][2][576];
    int sub = threadIdx.x >> 6;
    int t = threadIdx.x & 63;
    size_t line = (size_t)blockIdx.x * 4 + sub;
    const float2* src = d_Xs + line * FFT_N;
    float* dst = out + line * FFT_N;
    float2 a[8];
#pragma unroll
    for (int j = 0; j < 8; j++) a[j] = src[t + 64 * j];
    fft512r8<1>(a, t, sA[sub][0], sA[sub][1], sB[sub][0], sB[sub][1]);
    const float sc = 1.f / (float)NBIN;
#pragma unroll
    for (int m = 0; m < 8; m++) dst[t + 64 * m] = a[m].x * sc;
}

// ---------------- per-bin FDL solve (full spectrum, round-1 semantics) --------
// M = ATA + rho*I (8x8 Hermitian Toeplitz, HPD), rhs_c = A^H Y_c + rho*X_c.
// Cholesky once per bin, shared by 3 channels. Row (ky==256, kx in [1,255]) is
// zeroed to match the reference's unfilled padding row.
__global__ void __launch_bounds__(128) solve_kernel(const float* __restrict__ up,
                                                    const float* __restrict__ vp,
                                                    const float* __restrict__ rhop) {
    int bin = blockIdx.x * blockDim.x + threadIdx.x;
    int kx = bin & (FFT_N - 1);
    int ky = bin >> 9;
    float rho = rhop[0];

    if (ky == 256 && kx >= 1 && kx <= 255) {
        float2 z0 = make_float2(0.f, 0.f);
#pragma unroll
        for (int i = 0; i < NIMG_X; i++) d_Xs[(size_t)i * NBIN + bin] = z0;
        return;
    }

    float4 ex = d_etab[kx];
    float4 ey = d_etab[ky];
    float2 Edx = make_float2(ex.x, ex.y), E0x = make_float2(ex.z, ex.w);
    float2 Edy = make_float2(ey.x, ey.y), E0y = make_float2(ey.z, ey.w);

    float2 t[8];
#pragma unroll
    for (int m = 1; m < 8; m++) t[m] = make_float2(0.f, 0.f);

    float2 rhs[N_C][N_K];
#pragma unroll
    for (int c = 0; c < N_C; c++)
#pragma unroll
        for (int k = 0; k < N_K; k++) {
            float2 xv = d_Xs[((size_t)(c * N_K + k)) * NBIN + bin];
            rhs[c][k] = make_float2(rho * xv.x, rho * xv.y);
        }

#pragma unroll
    for (int vi = 0; vi < N_V; vi++) {
        float uu = up[vi], vv = vp[vi];
        float2 e  = cmulf2(cpowi(Edx, uu), cpowi(Edy, vv));   // exp(+i*delta*s_v)
        float2 e0 = cmulf2(cpowi(E0x, uu), cpowi(E0y, vv));   // exp(-i*d0*s_v)

        float2 p = e;
#pragma unroll
        for (int m = 1; m < 8; m++) { t[m] = caddf2(t[m], p); p = cmulf2(p, e); }

        float2 yv[N_C];
#pragma unroll
        for (int c = 0; c < N_C; c++) yv[c] = d_Ys[((size_t)(c * N_V + vi)) * NBIN + bin];

        float2 ak = e0;
        float2 ec = cconjf2(e);
#pragma unroll
        for (int k = 0; k < N_K; k++) {
#pragma unroll
            for (int c = 0; c < N_C; c++) {
                rhs[c][k].x = fmaf(ak.x, yv[c].x, fmaf(-ak.y, yv[c].y, rhs[c][k].x));
                rhs[c][k].y = fmaf(ak.x, yv[c].y, fmaf(ak.y, yv[c].x, rhs[c][k].y));
            }
            ak = cmulf2(ak, ec);
        }
    }

    // Cholesky of M = ATA + rho*I (Hermitian Toeplitz, diag = V + rho)
    float2 L[8][8];
    float di[8];
#pragma unroll
    for (int l = 0; l < 8; l++) {
        float ds = (float)N_V + rho;
#pragma unroll
        for (int j = 0; j < l; j++)
            ds -= L[l][j].x * L[l][j].x + L[l][j].y * L[l][j].y;
        float dl = sqrtf(ds);
        float inv = 1.f / dl;
        di[l] = inv;
#pragma unroll
        for (int k = l + 1; k < 8; k++) {
            float2 s = cconjf2(t[k - l]);
#pragma unroll
            for (int j = 0; j < l; j++)
                s = csubf2(s, cmulf2(L[k][j], cconjf2(L[l][j])));
            L[k][l] = make_float2(s.x * inv, s.y * inv);
        }
    }

#pragma unroll
    for (int c = 0; c < N_C; c++) {
        float2 w[8];
#pragma unroll
        for (int l = 0; l < 8; l++) {
            float2 s = rhs[c][l];
#pragma unroll
            for (int j = 0; j < l; j++) s = csubf2(s, cmulf2(L[l][j], w[j]));
            w[l] = make_float2(s.x * di[l], s.y * di[l]);
        }
        float2 z[8];
#pragma unroll
        for (int k = 7; k >= 0; k--) {
            float2 s = w[k];
#pragma unroll
            for (int j = k + 1; j < 8; j++) s = csubf2(s, cmulf2(cconjf2(L[j][k]), z[j]));
            z[k] = make_float2(s.x * di[k], s.y * di[k]);
        }
#pragma unroll
        for (int k = 0; k < N_K; k++)
            d_Xs[((size_t)(c * N_K + k)) * NBIN + bin] = z[k];
    }
}

// ---------------- launch ------------------------------------------------------
extern "C" void kernel_launch(void* const* d_in, const int* in_sizes, int n_in,
                              void* d_out, int out_size) {
    const float* x   = (const float*)d_in[0];  // [1,3,8,512,512]
    const float* y   = (const float*)d_in[1];  // [1,3,9,512,512]
    const float* u   = (const float*)d_in[2];  // [9]
    const float* v   = (const float*)d_in[3];  // [9]
    const float* dd  = (const float*)d_in[4];  // [8]
    const float* rho = (const float*)d_in[5];  // [1]
    float* out = (float*)d_out;                // [1,3,8,512,512] float32

    fill_tables<<<1, 512>>>(dd);

    // forward FFT2 (rows along W, then columns along H), full spectrum
    fwd_rows<0><<<NIMG_X * FFT_N / 4, 256>>>(x);
    fwd_rows<1><<<NIMG_Y * FFT_N / 4, 256>>>(y);
    fft_cols<0, 0><<<dim3(FFT_N / 4, NIMG_X), 256>>>();
    fft_cols<1, 0><<<dim3(FFT_N / 4, NIMG_Y), 256>>>();

    // per-frequency regularized least-squares solve (in-place into d_Xs)
    solve_kernel<<<NBIN / 128, 128>>>(u, v, rho);

    // inverse FFT2, write real part scaled by 1/(H*W)
    fft_cols<0, 1><<<dim3(FFT_N / 4, NIMG_X), 256>>>();
    inv_rows<<<NIMG_X * FFT_N / 4, 256>>>(out);
}

// round 5
// speedup vs baseline: 3.1717x; 1.7969x over previous
#include <cuda_runtime.h>
#include <cstdint>

#define FFT_N 512
#define NBIN (FFT_N * FFT_N)
#define N_C 3
#define N_K 8
#define N_V 9
#define NIMG_X (N_C * N_K)   // 24
#define NIMG_Y (N_C * N_V)   // 27
#define NKX 257              // half-spectrum columns kept (kx in [0,256])
#define PI_F 3.14159265358979323846f

// ---------------- scratch (static device globals; no cudaMalloc allowed) ----
__device__ float2 d_Xs[(size_t)NIMG_X * NBIN];   // X spectrum, reused as FDL spectrum
__device__ float2 d_Ys[(size_t)NIMG_Y * NBIN];   // Y spectrum
__device__ float2 d_tw[256];                     // W_512^j, j in [0,256)
__device__ float4 d_etab[FFT_N];                 // per-freq (exp(i*delta*w), exp(-i*d0*w))

// ---------------- complex helpers -------------------------------------------
__device__ __forceinline__ float2 cmulf2(float2 a, float2 b) {
    return make_float2(fmaf(a.x, b.x, -a.y * b.y), fmaf(a.x, b.y, a.y * b.x));
}
__device__ __forceinline__ float2 caddf2(float2 a, float2 b) { return make_float2(a.x + b.x, a.y + b.y); }
__device__ __forceinline__ float2 csubf2(float2 a, float2 b) { return make_float2(a.x - b.x, a.y - b.y); }
__device__ __forceinline__ float2 cconjf2(float2 a) { return make_float2(a.x, -a.y); }

__device__ __forceinline__ float2 cpowi(float2 z, float s) {
    if (s > 0.5f) return z;
    if (s < -0.5f) return cconjf2(z);
    return make_float2(1.f, 0.f);
}

// ---------------- table fill -------------------------------------------------
__global__ void fill_tables(const float* __restrict__ dp) {
    int j = threadIdx.x;
    if (j < 256) {
        float ang = -2.f * PI_F * (float)j / (float)FFT_N;
        float s, c;
        sincosf(ang, &s, &c);
        d_tw[j] = make_float2(c, s);
    }
    if (j < FFT_N) {
        float cf = (j < FFT_N / 2) ? (float)j : (float)(j - FFT_N);  // centered freq index
        float w = cf * (2.f * PI_F / (float)FFT_N);
        float delta = dp[1] - dp[0];
        float d0 = dp[0];
        float s1, c1, s2, c2;
        sincosf(delta * w, &s1, &c1);   // exp(+i*delta*w)
        sincosf(-d0 * w, &s2, &c2);     // exp(-i*d0*w)
        d_etab[j] = make_float4(c1, s1, c2, s2);
    }
}

// ---------------- register radix-8 butterflies --------------------------------
template <int INV>
__device__ __forceinline__ void fft4x(float2 v[4]) {
    float2 e0 = caddf2(v[0], v[2]), e1 = caddf2(v[1], v[3]);
    float2 o0 = csubf2(v[0], v[2]), o1 = csubf2(v[1], v[3]);
    o1 = INV ? make_float2(-o1.y, o1.x) : make_float2(o1.y, -o1.x);  // *(+-i)
    v[0] = caddf2(e0, e1); v[2] = csubf2(e0, e1);
    v[1] = caddf2(o0, o1); v[3] = csubf2(o0, o1);
}

template <int INV>
__device__ __forceinline__ void fft8(float2 a[8]) {
    const float C = 0.70710678118654752440f;
    float2 s[4], d[4];
#pragma unroll
    for (int k = 0; k < 4; k++) { s[k] = caddf2(a[k], a[k + 4]); d[k] = csubf2(a[k], a[k + 4]); }
    if (INV) {
        d[1] = cmulf2(d[1], make_float2(C, C));
        d[2] = make_float2(-d[2].y, d[2].x);
        d[3] = cmulf2(d[3], make_float2(-C, C));
    } else {
        d[1] = cmulf2(d[1], make_float2(C, -C));
        d[2] = make_float2(d[2].y, -d[2].x);
        d[3] = cmulf2(d[3], make_float2(-C, -C));
    }
    fft4x<INV>(s);
    fft4x<INV>(d);
    a[0] = s[0]; a[2] = s[1]; a[4] = s[2]; a[6] = s[3];
    a[1] = d[0]; a[3] = d[1]; a[5] = d[2]; a[7] = d[3];
}

// ---------------- 512-pt FFT: 64 threads, 8 regs, single-buffer (3 syncs) -----
// In:  a[j]  = x[t + 64*j],  t in [0,64)
// Out: a[m1] = X[t + 64*m1]
// Exchange A layout: [k0*72 + t]          Exchange B layout: [9*k0 + 72*m0 + r]
template <int INV>
__device__ __forceinline__ void fft512r8(float2 a[8], int t, float* re, float* im) {
    fft8<INV>(a);
    {   // a[k0] *= W512^{t*k0}
        float2 w = d_tw[t]; if (INV) w.y = -w.y;
        float2 p = w;
#pragma unroll
        for (int k = 1; k < 8; k++) { a[k] = cmulf2(a[k], p); p = cmulf2(p, w); }
    }
#pragma unroll
    for (int k = 0; k < 8; k++) { re[k * 72 + t] = a[k].x; im[k * 72 + t] = a[k].y; }
    __syncthreads();
    int hi = t >> 3, lo = t & 7;
#pragma unroll
    for (int j = 0; j < 8; j++) {
        int idx = hi * 72 + 8 * j + lo;
        a[j] = make_float2(re[idx], im[idx]);
    }
    __syncthreads();                               // all reads done before overwrite
    fft8<INV>(a);
    {   // a[m0] *= W64^{lo*m0} = W512^{8*lo*m0}
        float2 w = d_tw[8 * lo]; if (INV) w.y = -w.y;
        float2 p = w;
#pragma unroll
        for (int m = 1; m < 8; m++) { a[m] = cmulf2(a[m], p); p = cmulf2(p, w); }
    }
#pragma unroll
    for (int m = 0; m < 8; m++) {
        int idx = 9 * hi + 72 * m + lo;
        re[idx] = a[m].x; im[idx] = a[m].y;
    }
    __syncthreads();
#pragma unroll
    for (int r = 0; r < 8; r++) {
        int idx = 9 * lo + 72 * hi + r;
        a[r] = make_float2(re[idx], im[idx]);
    }
    fft8<INV>(a);
}

// ---------------- row FFT: real input -> half spectrum (kx in [0,256]) -------
template <int WHICH>  // 0 -> d_Xs, 1 -> d_Ys
__global__ void fwd_rows(const float* __restrict__ in) {
    __shared__ float s[4 * 1160];
    int sub = threadIdx.x >> 6;       // 4 rows per 256-thread block
    int t = threadIdx.x & 63;
    size_t line = (size_t)blockIdx.x * 4 + sub;
    const float* src = in + line * FFT_N;
    float2* dst = (WHICH ? d_Ys : d_Xs) + line * FFT_N;
    float2 a[8];
#pragma unroll
    for (int j = 0; j < 8; j++) a[j] = make_float2(src[t + 64 * j], 0.f);
    float* base = s + sub * 1160;
    fft512r8<0>(a, t, base, base + 576);
#pragma unroll
    for (int m = 0; m < 8; m++) {
        int idx = t + 64 * m;
        if (idx < NKX) dst[idx] = a[m];
    }
}

// ---------------- column FFT (along H) on half-spectrum columns ---------------
// 4 columns per 256-thread block; slice stride 1160 floats (== 8 mod 32:
// conflict-free for the c = tid&3 interleave in all exchange phases).
template <int WHICH, int INV>
__global__ void fft_cols(void) {
    __shared__ float s[4 * 1160];
    float2* data = (WHICH ? d_Ys : d_Xs) + (size_t)blockIdx.y * NBIN;
    int c = threadIdx.x & 3;
    int t = threadIdx.x >> 2;         // [0,64)
    int kx = blockIdx.x * 4 + c;
    bool act = (kx < NKX);
    float2* col = data + kx;
    float2 a[8];
#pragma unroll
    for (int j = 0; j < 8; j++)
        a[j] = act ? col[(size_t)(t + 64 * j) * FFT_N] : make_float2(0.f, 0.f);
    float* base = s + c * 1160;
    fft512r8<INV>(a, t, base, base + 576);
#pragma unroll
    for (int m = 0; m < 8; m++)
        if (act) col[(size_t)(t + 64 * m) * FFT_N] = a[m];
}

// ---------------- inverse row FFT: half spectrum -> real output ---------------
__global__ void inv_rows(float* __restrict__ out) {
    __shared__ float s[4 * 1160];
    int sub = threadIdx.x >> 6;
    int t = threadIdx.x & 63;
    size_t line = (size_t)blockIdx.x * 4 + sub;
    const float2* src = d_Xs + line * FFT_N;
    float* dst = out + line * FFT_N;
    float2 a[8];
#pragma unroll
    for (int j = 0; j < 8; j++) {
        int idx = t + 64 * j;
        if (idx < NKX) a[j] = src[idx];
        else { float2 m = src[FFT_N - idx]; a[j] = make_float2(m.x, -m.y); }  // Hermitian
    }
    float* base = s + sub * 1160;
    fft512r8<1>(a, t, base, base + 576);
    const float sc = 1.f / (float)NBIN;
#pragma unroll
    for (int m = 0; m < 8; m++) dst[t + 64 * m] = a[m].x * sc;
}

// ---------------- per-bin FDL solve (half spectrum) ----------------------------
// Bins: ky in [0,512), kx in [0,257).
// Row (ky==256, kx in [1,255]): reference leaves these zero and keeps the mirror
// bins solved at wy=-pi. Effective Hermitian spectrum there:
// conj(solve(256,512-kx))/2 = [solve with wy conjugated, local data] * 0.5.
// Columns kx in {0,256}: direct solve; the final Re() extraction auto-Hermitizes.
__global__ void __launch_bounds__(128) solve_kernel(const float* __restrict__ up,
                                                    const float* __restrict__ vp,
                                                    const float* __restrict__ rhop) {
    int bidx = blockIdx.x * blockDim.x + threadIdx.x;   // 512*257 = 131584 bins
    int ky = bidx / NKX;
    int kx = bidx - ky * NKX;
    int bin = ky * FFT_N + kx;
    float rho = rhop[0];

    float4 ex = d_etab[kx];
    float4 ey = d_etab[ky];
    float2 Edx = make_float2(ex.x, ex.y), E0x = make_float2(ex.z, ex.w);
    float2 Edy = make_float2(ey.x, ey.y), E0y = make_float2(ey.z, ey.w);

    bool mirror_row = (ky == 256 && kx >= 1 && kx <= 255);
    float hsc = mirror_row ? 0.5f : 1.0f;
    if (mirror_row) { Edy = cconjf2(Edy); E0y = cconjf2(E0y); }   // wy: -pi -> +pi

    float2 t[8];
#pragma unroll
    for (int m = 1; m < 8; m++) t[m] = make_float2(0.f, 0.f);

    float2 rhs[N_C][N_K];
#pragma unroll
    for (int c = 0; c < N_C; c++)
#pragma unroll
        for (int k = 0; k < N_K; k++) {
            float2 xv = d_Xs[((size_t)(c * N_K + k)) * NBIN + bin];
            rhs[c][k] = make_float2(rho * xv.x, rho * xv.y);
        }

#pragma unroll
    for (int vi = 0; vi < N_V; vi++) {
        float uu = up[vi], vv = vp[vi];
        float2 e  = cmulf2(cpowi(Edx, uu), cpowi(Edy, vv));   // exp(+i*delta*s_v)
        float2 e0 = cmulf2(cpowi(E0x, uu), cpowi(E0y, vv));   // exp(-i*d0*s_v)

        float2 p = e;
#pragma unroll
        for (int m = 1; m < 8; m++) { t[m] = caddf2(t[m], p); p = cmulf2(p, e); }

        float2 yv[N_C];
#pragma unroll
        for (int c = 0; c < N_C; c++) yv[c] = d_Ys[((size_t)(c * N_V + vi)) * NBIN + bin];

        float2 ak = e0;
        float2 ec = cconjf2(e);
#pragma unroll
        for (int k = 0; k < N_K; k++) {
#pragma unroll
            for (int c = 0; c < N_C; c++) {
                rhs[c][k].x = fmaf(ak.x, yv[c].x, fmaf(-ak.y, yv[c].y, rhs[c][k].x));
                rhs[c][k].y = fmaf(ak.x, yv[c].y, fmaf(ak.y, yv[c].x, rhs[c][k].y));
            }
            ak = cmulf2(ak, ec);
        }
    }

    // Cholesky of M = ATA + rho*I (Hermitian Toeplitz, diag = V + rho)
    float2 L[8][8];
    float di[8];
#pragma unroll
    for (int l = 0; l < 8; l++) {
        float ds = (float)N_V + rho;
#pragma unroll
        for (int j = 0; j < l; j++)
            ds -= L[l][j].x * L[l][j].x + L[l][j].y * L[l][j].y;
        float dl = sqrtf(ds);
        float inv = 1.f / dl;
        di[l] = inv;
#pragma unroll
        for (int k = l + 1; k < 8; k++) {
            float2 s = cconjf2(t[k - l]);
#pragma unroll
            for (int j = 0; j < l; j++)
                s = csubf2(s, cmulf2(L[k][j], cconjf2(L[l][j])));
            L[k][l] = make_float2(s.x * inv, s.y * inv);
        }
    }

#pragma unroll
    for (int c = 0; c < N_C; c++) {
        float2 w[8];
#pragma unroll
        for (int l = 0; l < 8; l++) {
            float2 s = rhs[c][l];
#pragma unroll
            for (int j = 0; j < l; j++) s = csubf2(s, cmulf2(L[l][j], w[j]));
            w[l] = make_float2(s.x * di[l], s.y * di[l]);
        }
        float2 z[8];
#pragma unroll
        for (int k = 7; k >= 0; k--) {
            float2 s = w[k];
#pragma unroll
            for (int j = k + 1; j < 8; j++) s = csubf2(s, cmulf2(cconjf2(L[j][k]), z[j]));
            z[k] = make_float2(s.x * di[k], s.y * di[k]);   // UNSCALED back-substitution
        }
        // apply mirror-row half-weight AFTER the solve completes (round-3 bug fix)
#pragma unroll
        for (int k = 0; k < N_K; k++)
            d_Xs[((size_t)(c * N_K + k)) * NBIN + bin] = make_float2(z[k].x * hsc, z[k].y * hsc);
    }
}

// ---------------- launch ------------------------------------------------------
extern "C" void kernel_launch(void* const* d_in, const int* in_sizes, int n_in,
                              void* d_out, int out_size) {
    const float* x   = (const float*)d_in[0];  // [1,3,8,512,512]
    const float* y   = (const float*)d_in[1];  // [1,3,9,512,512]
    const float* u   = (const float*)d_in[2];  // [9]
    const float* v   = (const float*)d_in[3];  // [9]
    const float* dd  = (const float*)d_in[4];  // [8]
    const float* rho = (const float*)d_in[5];  // [1]
    float* out = (float*)d_out;                // [1,3,8,512,512] float32

    fill_tables<<<1, 512>>>(dd);

    // forward: rows (R2C, keep kx<=256), then columns on 257 kept columns
    fwd_rows<0><<<NIMG_X * FFT_N / 4, 256>>>(x);
    fwd_rows<1><<<NIMG_Y * FFT_N / 4, 256>>>(y);
    fft_cols<0, 0><<<dim3((NKX + 3) / 4, NIMG_X), 256>>>();
    fft_cols<1, 0><<<dim3((NKX + 3) / 4, NIMG_Y), 256>>>();

    // per-frequency regularized least-squares solve (half spectrum, in-place)
    solve_kernel<<<(FFT_N * NKX) / 128, 128>>>(u, v, rho);

    // inverse: columns on 257 columns, then rows C2R with Hermitian reconstruction
    fft_cols<0, 1><<<dim3((NKX + 3) / 4, NIMG_X), 256>>>();
    inv_rows<<<NIMG_X * FFT_N / 4, 256>>>(out);
}

// round 6
// speedup vs baseline: 3.6870x; 1.1625x over previous
#include <cuda_runtime.h>
#include <cstdint>

#define FFT_N 512
#define NBIN (FFT_N * FFT_N)
#define N_C 3
#define N_K 8
#define N_V 9
#define NIMG_X (N_C * N_K)   // 24
#define NIMG_Y (N_C * N_V)   // 27
#define NKX 257              // half-spectrum columns kept (kx in [0,256])
#define PI_F 3.14159265358979323846f

// ---------------- scratch (static device globals; no cudaMalloc allowed) ----
__device__ float2 d_Xs[(size_t)NIMG_X * NBIN];   // X spectrum, reused as FDL spectrum
__device__ float2 d_Ys[(size_t)NIMG_Y * NBIN];   // Y spectrum
__device__ float2 d_tw[256];                     // W_512^j, j in [0,256)
__device__ float4 d_etab[FFT_N];                 // per-freq (exp(i*delta*w), exp(-i*d0*w))

// ---------------- complex helpers -------------------------------------------
__device__ __forceinline__ float2 cmulf2(float2 a, float2 b) {
    return make_float2(fmaf(a.x, b.x, -a.y * b.y), fmaf(a.x, b.y, a.y * b.x));
}
__device__ __forceinline__ float2 caddf2(float2 a, float2 b) { return make_float2(a.x + b.x, a.y + b.y); }
__device__ __forceinline__ float2 csubf2(float2 a, float2 b) { return make_float2(a.x - b.x, a.y - b.y); }
__device__ __forceinline__ float2 cconjf2(float2 a) { return make_float2(a.x, -a.y); }

__device__ __forceinline__ float2 cpowi(float2 z, float s) {
    if (s > 0.5f) return z;
    if (s < -0.5f) return cconjf2(z);
    return make_float2(1.f, 0.f);
}

// ---------------- table fill -------------------------------------------------
__global__ void fill_tables(const float* __restrict__ dp) {
    int j = threadIdx.x;
    if (j < 256) {
        float ang = -2.f * PI_F * (float)j / (float)FFT_N;
        float s, c;
        sincosf(ang, &s, &c);
        d_tw[j] = make_float2(c, s);
    }
    if (j < FFT_N) {
        float cf = (j < FFT_N / 2) ? (float)j : (float)(j - FFT_N);  // centered freq index
        float w = cf * (2.f * PI_F / (float)FFT_N);
        float delta = dp[1] - dp[0];
        float d0 = dp[0];
        float s1, c1, s2, c2;
        sincosf(delta * w, &s1, &c1);   // exp(+i*delta*w)
        sincosf(-d0 * w, &s2, &c2);     // exp(-i*d0*w)
        d_etab[j] = make_float4(c1, s1, c2, s2);
    }
}

// ---------------- register radix-8 butterflies --------------------------------
template <int INV>
__device__ __forceinline__ void fft4x(float2 v[4]) {
    float2 e0 = caddf2(v[0], v[2]), e1 = caddf2(v[1], v[3]);
    float2 o0 = csubf2(v[0], v[2]), o1 = csubf2(v[1], v[3]);
    o1 = INV ? make_float2(-o1.y, o1.x) : make_float2(o1.y, -o1.x);  // *(+-i)
    v[0] = caddf2(e0, e1); v[2] = csubf2(e0, e1);
    v[1] = caddf2(o0, o1); v[3] = csubf2(o0, o1);
}

template <int INV>
__device__ __forceinline__ void fft8(float2 a[8]) {
    const float C = 0.70710678118654752440f;
    float2 s[4], d[4];
#pragma unroll
    for (int k = 0; k < 4; k++) { s[k] = caddf2(a[k], a[k + 4]); d[k] = csubf2(a[k], a[k + 4]); }
    if (INV) {
        d[1] = cmulf2(d[1], make_float2(C, C));
        d[2] = make_float2(-d[2].y, d[2].x);
        d[3] = cmulf2(d[3], make_float2(-C, C));
    } else {
        d[1] = cmulf2(d[1], make_float2(C, -C));
        d[2] = make_float2(d[2].y, -d[2].x);
        d[3] = cmulf2(d[3], make_float2(-C, -C));
    }
    fft4x<INV>(s);
    fft4x<INV>(d);
    a[0] = s[0]; a[2] = s[1]; a[4] = s[2]; a[6] = s[3];
    a[1] = d[0]; a[3] = d[1]; a[5] = d[2]; a[7] = d[3];
}

// ---------------- 512-pt FFT: 64 threads, 8 regs, single-buffer (3 syncs) -----
// In:  a[j]  = x[t + 64*j],  t in [0,64)
// Out: a[m1] = X[t + 64*m1]
// Exchange A layout: [k0*72 + t]          Exchange B layout: [9*k0 + 72*m0 + r]
template <int INV>
__device__ __forceinline__ void fft512r8(float2 a[8], int t, float* re, float* im) {
    fft8<INV>(a);
    {   // a[k0] *= W512^{t*k0}
        float2 w = d_tw[t]; if (INV) w.y = -w.y;
        float2 p = w;
#pragma unroll
        for (int k = 1; k < 8; k++) { a[k] = cmulf2(a[k], p); p = cmulf2(p, w); }
    }
#pragma unroll
    for (int k = 0; k < 8; k++) { re[k * 72 + t] = a[k].x; im[k * 72 + t] = a[k].y; }
    __syncthreads();
    int hi = t >> 3, lo = t & 7;
#pragma unroll
    for (int j = 0; j < 8; j++) {
        int idx = hi * 72 + 8 * j + lo;
        a[j] = make_float2(re[idx], im[idx]);
    }
    __syncthreads();                               // all reads done before overwrite
    fft8<INV>(a);
    {   // a[m0] *= W64^{lo*m0} = W512^{8*lo*m0}
        float2 w = d_tw[8 * lo]; if (INV) w.y = -w.y;
        float2 p = w;
#pragma unroll
        for (int m = 1; m < 8; m++) { a[m] = cmulf2(a[m], p); p = cmulf2(p, w); }
    }
#pragma unroll
    for (int m = 0; m < 8; m++) {
        int idx = 9 * hi + 72 * m + lo;
        re[idx] = a[m].x; im[idx] = a[m].y;
    }
    __syncthreads();
#pragma unroll
    for (int r = 0; r < 8; r++) {
        int idx = 9 * lo + 72 * hi + r;
        a[r] = make_float2(re[idx], im[idx]);
    }
    fft8<INV>(a);
}

// ---------------- row FFT (X and Y in ONE launch): real -> half spectrum ------
__global__ void fwd_rows_all(const float* __restrict__ xin, const float* __restrict__ yin) {
    __shared__ float s[4 * 1160];
    int blk = blockIdx.x;
    const float* in;
    float2* outp;
    if (blk < NIMG_X * (FFT_N / 4)) { in = xin; outp = d_Xs; }
    else { blk -= NIMG_X * (FFT_N / 4); in = yin; outp = d_Ys; }
    int sub = threadIdx.x >> 6;       // 4 rows per 256-thread block
    int t = threadIdx.x & 63;
    size_t line = (size_t)blk * 4 + sub;
    const float* src = in + line * FFT_N;
    float2* dst = outp + line * FFT_N;
    float2 a[8];
#pragma unroll
    for (int j = 0; j < 8; j++) a[j] = make_float2(src[t + 64 * j], 0.f);
    float* base = s + sub * 1160;
    fft512r8<0>(a, t, base, base + 576);
#pragma unroll
    for (int m = 0; m < 8; m++) {
        int idx = t + 64 * m;
        if (idx < NKX) dst[idx] = a[m];
    }
}

// ---------------- forward column FFT (X and Y planes in ONE launch) -----------
__global__ void fft_cols_fwd(void) {
    __shared__ float s[4 * 1160];
    int p = blockIdx.y;
    float2* data = (p < NIMG_X) ? d_Xs + (size_t)p * NBIN
                                : d_Ys + (size_t)(p - NIMG_X) * NBIN;
    int c = threadIdx.x & 3;
    int t = threadIdx.x >> 2;         // [0,64)
    int kx = blockIdx.x * 4 + c;
    bool act = (kx < NKX);
    float2* col = data + kx;
    float2 a[8];
#pragma unroll
    for (int j = 0; j < 8; j++)
        a[j] = act ? col[(size_t)(t + 64 * j) * FFT_N] : make_float2(0.f, 0.f);
    float* base = s + c * 1160;
    fft512r8<0>(a, t, base, base + 576);
#pragma unroll
    for (int m = 0; m < 8; m++)
        if (act) col[(size_t)(t + 64 * m) * FFT_N] = a[m];
}

// ---------------- inverse column FFT (X planes) --------------------------------
__global__ void fft_cols_inv(void) {
    __shared__ float s[4 * 1160];
    float2* data = d_Xs + (size_t)blockIdx.y * NBIN;
    int c = threadIdx.x & 3;
    int t = threadIdx.x >> 2;
    int kx = blockIdx.x * 4 + c;
    bool act = (kx < NKX);
    float2* col = data + kx;
    float2 a[8];
#pragma unroll
    for (int j = 0; j < 8; j++)
        a[j] = act ? col[(size_t)(t + 64 * j) * FFT_N] : make_float2(0.f, 0.f);
    float* base = s + c * 1160;
    fft512r8<1>(a, t, base, base + 576);
#pragma unroll
    for (int m = 0; m < 8; m++)
        if (act) col[(size_t)(t + 64 * m) * FFT_N] = a[m];
}

// ---------------- inverse row FFT: half spectrum -> real output ---------------
__global__ void inv_rows(float* __restrict__ out) {
    __shared__ float s[4 * 1160];
    int sub = threadIdx.x >> 6;
    int t = threadIdx.x & 63;
    size_t line = (size_t)blockIdx.x * 4 + sub;
    const float2* src = d_Xs + line * FFT_N;
    float* dst = out + line * FFT_N;
    float2 a[8];
#pragma unroll
    for (int j = 0; j < 8; j++) {
        int idx = t + 64 * j;
        if (idx < NKX) a[j] = src[idx];
        else { float2 m = src[FFT_N - idx]; a[j] = make_float2(m.x, -m.y); }  // Hermitian
    }
    float* base = s + sub * 1160;
    fft512r8<1>(a, t, base, base + 576);
    const float sc = 1.f / (float)NBIN;
#pragma unroll
    for (int m = 0; m < 8; m++) dst[t + 64 * m] = a[m].x * sc;
}

// ---------------- per-bin FDL solve (half spectrum, REAL Toeplitz Gram) -------
// Views form the full 3x3 grid (u,v in {-1,0,1}^2), so
//   t[m] = sum_v exp(i m d (u wx + v wy)) = (1+2cos(m d wx)) (1+2cos(m d wy))
// is REAL => M = ATA + rho*I is real symmetric Toeplitz. Real Cholesky, then
// real-L x complex-rhs substitutions (2 FMA per term).
// Row (ky==256, kx in [1,255]): conjugate y-exponentials for the rhs (cos terms
// unchanged), scale result by 0.5 (reference's Hermitian-averaged padding row).
__global__ void __launch_bounds__(256) solve_kernel(const float* __restrict__ up,
                                                    const float* __restrict__ vp,
                                                    const float* __restrict__ rhop) {
    int bidx = blockIdx.x * blockDim.x + threadIdx.x;   // 512*257 = 131584 bins
    int ky = bidx / NKX;
    int kx = bidx - ky * NKX;
    int bin = ky * FFT_N + kx;
    float rho = rhop[0];

    float4 ex = d_etab[kx];
    float4 ey = d_etab[ky];
    float2 Edx = make_float2(ex.x, ex.y), E0x = make_float2(ex.z, ex.w);
    float2 Edy = make_float2(ey.x, ey.y), E0y = make_float2(ey.z, ey.w);

    bool mirror_row = (ky == 256 && kx >= 1 && kx <= 255);
    float hsc = mirror_row ? 0.5f : 1.0f;
    if (mirror_row) { Edy = cconjf2(Edy); E0y = cconjf2(E0y); }   // wy: -pi -> +pi

    // real Toeplitz generators t[m] = (1+2cos(m d wx))(1+2cos(m d wy))
    float tmr[8];
    {
        float axc = Edx.x, ayc = Edy.x;
        float cx1 = 1.f, cx = axc;     // cos(0), cos(1*th)
        float cy1 = 1.f, cy = ayc;
#pragma unroll
        for (int m = 1; m < 8; m++) {
            tmr[m] = (1.f + 2.f * cx) * (1.f + 2.f * cy);
            float nx = fmaf(2.f * axc, cx, -cx1); cx1 = cx; cx = nx;
            float ny = fmaf(2.f * ayc, cy, -cy1); cy1 = cy; cy = ny;
        }
    }

    // rhs = A^H Y + rho X  (complex; uses actual u,v values)
    float2 rhs[N_C][N_K];
#pragma unroll
    for (int c = 0; c < N_C; c++)
#pragma unroll
        for (int k = 0; k < N_K; k++) {
            float2 xv = d_Xs[((size_t)(c * N_K + k)) * NBIN + bin];
            rhs[c][k] = make_float2(rho * xv.x, rho * xv.y);
        }

#pragma unroll
    for (int vi = 0; vi < N_V; vi++) {
        float uu = up[vi], vv = vp[vi];
        float2 e  = cmulf2(cpowi(Edx, uu), cpowi(Edy, vv));   // exp(+i*delta*s_v)
        float2 e0 = cmulf2(cpowi(E0x, uu), cpowi(E0y, vv));   // exp(-i*d0*s_v)

        float2 yv[N_C];
#pragma unroll
        for (int c = 0; c < N_C; c++) yv[c] = d_Ys[((size_t)(c * N_V + vi)) * NBIN + bin];

        float2 ak = e0;
        float2 ec = cconjf2(e);
#pragma unroll
        for (int k = 0; k < N_K; k++) {
#pragma unroll
            for (int c = 0; c < N_C; c++) {
                rhs[c][k].x = fmaf(ak.x, yv[c].x, fmaf(-ak.y, yv[c].y, rhs[c][k].x));
                rhs[c][k].y = fmaf(ak.x, yv[c].y, fmaf(ak.y, yv[c].x, rhs[c][k].y));
            }
            ak = cmulf2(ak, ec);
        }
    }

    // real Cholesky of M (diag = 9 + rho, off-diag t[|k-l|])
    float L[8][8];
    float di[8];
#pragma unroll
    for (int l = 0; l < 8; l++) {
        float ds = (float)N_V + rho;
#pragma unroll
        for (int j = 0; j < l; j++) ds = fmaf(-L[l][j], L[l][j], ds);
        float inv = rsqrtf(ds);
        di[l] = inv;
#pragma unroll
        for (int k = l + 1; k < 8; k++) {
            float s = tmr[k - l];
#pragma unroll
            for (int j = 0; j < l; j++) s = fmaf(-L[k][j], L[l][j], s);
            L[k][l] = s * inv;
        }
    }

#pragma unroll
    for (int c = 0; c < N_C; c++) {
        float2 w[8];
#pragma unroll
        for (int l = 0; l < 8; l++) {
            float2 s = rhs[c][l];
#pragma unroll
            for (int j = 0; j < l; j++) {
                s.x = fmaf(-L[l][j], w[j].x, s.x);
                s.y = fmaf(-L[l][j], w[j].y, s.y);
            }
            w[l] = make_float2(s.x * di[l], s.y * di[l]);
        }
        float2 z[8];
#pragma unroll
        for (int k = 7; k >= 0; k--) {
            float2 s = w[k];
#pragma unroll
            for (int j = k + 1; j < 8; j++) {
                s.x = fmaf(-L[j][k], z[j].x, s.x);
                s.y = fmaf(-L[j][k], z[j].y, s.y);
            }
            z[k] = make_float2(s.x * di[k], s.y * di[k]);
        }
#pragma unroll
        for (int k = 0; k < N_K; k++)
            d_Xs[((size_t)(c * N_K + k)) * NBIN + bin] = make_float2(z[k].x * hsc, z[k].y * hsc);
    }
}

// ---------------- launch ------------------------------------------------------
extern "C" void kernel_launch(void* const* d_in, const int* in_sizes, int n_in,
                              void* d_out, int out_size) {
    const float* x   = (const float*)d_in[0];  // [1,3,8,512,512]
    const float* y   = (const float*)d_in[1];  // [1,3,9,512,512]
    const float* u   = (const float*)d_in[2];  // [9]
    const float* v   = (const float*)d_in[3];  // [9]
    const float* dd  = (const float*)d_in[4];  // [8]
    const float* rho = (const float*)d_in[5];  // [1]
    float* out = (float*)d_out;                // [1,3,8,512,512] float32

    fill_tables<<<1, 512>>>(dd);

    // forward: all 51 planes of row FFTs in one launch, then all column FFTs
    fwd_rows_all<<<(NIMG_X + NIMG_Y) * (FFT_N / 4), 256>>>(x, y);
    fft_cols_fwd<<<dim3((NKX + 3) / 4, NIMG_X + NIMG_Y), 256>>>();

    // per-frequency regularized least-squares solve (half spectrum, in-place)
    solve_kernel<<<(FFT_N * NKX) / 256, 256>>>(u, v, rho);

    // inverse: columns on 257 columns, then rows C2R with Hermitian reconstruction
    fft_cols_inv<<<dim3((NKX + 3) / 4, NIMG_X), 256>>>();
    inv_rows<<<NIMG_X * FFT_N / 4, 256>>>(out);
}